// round 1
// baseline (speedup 1.0000x reference)
#include <cuda_runtime.h>

#define NG      1024
#define IMG_W   256
#define IMG_H   256
#define TILE_SZ 64
#define NT      16
#define FOCALF  256.0f   // W / (2 * TAN_FOV) = 256 / 1

// ---------------- device scratch (no allocs allowed) ----------------
__device__ unsigned long long g_key[NG];
__device__ float4 g_uA[NG], g_uB[NG], g_uR[NG];   // unsorted: A=(mx,my,k,op) B=(r,g,b,dep) R=rect
__device__ float4 g_sA[NG], g_sB[NG], g_sR[NG];   // depth-sorted
__device__ float4 g_tA[NT][NG], g_tB[NT][NG];     // per-tile compacted, depth order
__device__ int    g_tcount[NT];

// ---------------- 1) project gaussians ----------------
__global__ void k_project(const float* __restrict__ means3d,
                          const float* __restrict__ opacity,
                          const float* __restrict__ scale3d,
                          const float* __restrict__ features,
                          const float* __restrict__ V,
                          const float* __restrict__ P) {
    int g = blockIdx.x * blockDim.x + threadIdx.x;
    if (g >= NG) return;
    float x = means3d[3*g+0], y = means3d[3*g+1], z = means3d[3*g+2];

    // pv = [x y z 1] @ V  (row-vector convention, V row-major)
    float pv0 = x*V[0] + y*V[4] + z*V[8]  + V[12];
    float pv1 = x*V[1] + y*V[5] + z*V[9]  + V[13];
    float pv2 = x*V[2] + y*V[6] + z*V[10] + V[14];
    float pv3 = x*V[3] + y*V[7] + z*V[11] + V[15];

    // ph = pv @ P  (only x, y, w needed)
    float ph0 = pv0*P[0] + pv1*P[4] + pv2*P[8]  + pv3*P[12];
    float ph1 = pv0*P[1] + pv1*P[5] + pv2*P[9]  + pv3*P[13];
    float ph3 = pv0*P[3] + pv1*P[7] + pv2*P[11] + pv3*P[15];

    float invw = 1.0f / (ph3 + 1e-6f);
    float mx = ((ph0*invw + 1.0f) * (float)IMG_W - 1.0f) * 0.5f;
    float my = ((ph1*invw + 1.0f) * (float)IMG_H - 1.0f) * 0.5f;

    float tz    = pv2;                       // depth (viewmatrix row [3][2] handled above)
    float s2    = scale3d[g] * FOCALF / tz;  // scale2d (both components equal)
    float radii = s2 * 5.0f;                 // RADII_MULT
    float kk    = -0.5f / (s2 * s2);         // exp coefficient

    float rminx = fminf(fmaxf(mx - radii, 0.0f), (float)IMG_W - 1.0f);
    float rminy = fminf(fmaxf(my - radii, 0.0f), (float)IMG_H - 1.0f);
    float rmaxx = fminf(fmaxf(mx + radii, 0.0f), (float)IMG_W - 1.0f);
    float rmaxy = fminf(fmaxf(my + radii, 0.0f), (float)IMG_H - 1.0f);

    g_uA[g] = make_float4(mx, my, kk, opacity[g]);
    g_uB[g] = make_float4(features[3*g+0], features[3*g+1], features[3*g+2], tz);
    g_uR[g] = make_float4(rminx, rminy, rmaxx, rmaxy);

    // stable order-preserving key: (flip(depth_bits) << 32) | index
    unsigned ku = __float_as_uint(tz);
    ku = (ku & 0x80000000u) ? ~ku : (ku | 0x80000000u);
    g_key[g] = ((unsigned long long)ku << 32) | (unsigned)g;
}

// ---------------- 2) rank sort (stable via unique keys) ----------------
__global__ void k_sort() {
    __shared__ unsigned long long keys[NG];
    int tid = threadIdx.x;
    for (int i = tid; i < NG; i += blockDim.x) keys[i] = g_key[i];
    __syncthreads();

    int g = blockIdx.x * blockDim.x + tid;   // 8 blocks * 128 threads = 1024
    unsigned long long myk = keys[g];
    int r = 0;
    #pragma unroll 16
    for (int j = 0; j < NG; j++) r += (keys[j] < myk) ? 1 : 0;

    g_sA[r] = g_uA[g];
    g_sB[r] = g_uB[g];
    g_sR[r] = g_uR[g];
}

// ---------------- 3) per-tile ordered compaction ----------------
__global__ void k_compact() {
    int t = blockIdx.x;           // tile 0..15
    int g = threadIdx.x;          // sorted gaussian index, 1024 threads
    float u0 = (float)((t & 3) * TILE_SZ);
    float v0 = (float)((t >> 2) * TILE_SZ);

    float4 R = g_sR[g];
    float tlx = fmaxf(R.x, u0);
    float tly = fmaxf(R.y, v0);
    float brx = fminf(R.z, u0 + (float)TILE_SZ - 1.0f);
    float bry = fminf(R.w, v0 + (float)TILE_SZ - 1.0f);
    bool m = (brx > tlx) && (bry > tly);

    int wid = g >> 5, lane = g & 31;
    unsigned bal = __ballot_sync(0xffffffffu, m);
    int inwarp = __popc(bal & ((1u << lane) - 1u));

    __shared__ int wsum[32];
    if (lane == 0) wsum[wid] = __popc(bal);
    __syncthreads();
    if (wid == 0) {
        int v = wsum[lane];
        #pragma unroll
        for (int off = 1; off < 32; off <<= 1) {
            int nv = __shfl_up_sync(0xffffffffu, v, off);
            if (lane >= off) v += nv;
        }
        wsum[lane] = v;   // inclusive scan of warp totals
    }
    __syncthreads();

    int base = (wid == 0) ? 0 : wsum[wid - 1];
    if (m) {
        int pos = base + inwarp;
        g_tA[t][pos] = g_sA[g];
        g_tB[t][pos] = g_sB[g];
    }
    if (g == NG - 1) g_tcount[t] = wsum[31];
}

// ---------------- 4) render: 256 blocks, 16x16 px each ----------------
__global__ void __launch_bounds__(256) k_render(float* __restrict__ out) {
    int b = blockIdx.x;
    int tileIdx = b >> 4;              // parent 64x64 tile
    int sub     = b & 15;              // 4x4 sub-blocks of 16x16 px
    int px0 = (tileIdx & 3) * TILE_SZ + (sub & 3) * 16;
    int py0 = (tileIdx >> 2) * TILE_SZ + (sub >> 2) * 16;

    int tid = threadIdx.x;
    int px = px0 + (tid & 15);
    int py = py0 + (tid >> 4);
    float fx = (float)px, fy = (float)py;

    int count = g_tcount[tileIdx];
    const float4* __restrict__ TA = g_tA[tileIdx];
    const float4* __restrict__ TB = g_tB[tileIdx];

    __shared__ float4 sA[256];
    __shared__ float4 sB[256];

    float T = 1.0f, acc = 0.0f, cr = 0.0f, cg = 0.0f, cb = 0.0f, dsum = 0.0f;

    for (int c0 = 0; c0 < count; c0 += 256) {
        // uniform early exit: remaining contribution bounded by T < 1e-6
        if (__syncthreads_count(T > 1e-6f) == 0) break;

        int i = c0 + tid;
        if (i < count) { sA[tid] = TA[i]; sB[tid] = TB[i]; }
        __syncthreads();

        int n = min(256, count - c0);
        for (int j = 0; j < n; j++) {
            float4 A = sA[j];
            float dx = fx - A.x;
            float dy = fy - A.y;
            float d2 = dx*dx + dy*dy;
            float e  = __expf(A.z * d2);
            float a  = fminf(e * A.w, 0.99f);
            float w  = a * T;
            float4 B = sB[j];
            acc  += w;
            cr   += w * B.x;
            cg   += w * B.y;
            cb   += w * B.z;
            dsum += w * B.w;
            T    -= w;
            if ((j & 63) == 63) {
                if (__all_sync(0xffffffffu, T <= 1e-6f)) break;  // warp-level exit
            }
        }
        __syncthreads();
    }

    float bg = 1.0f - acc;
    int pix = py * IMG_W + px;
    out[pix*3 + 0] = fminf(fmaxf(cr + bg, 0.0f), 1.0f);
    out[pix*3 + 1] = fminf(fmaxf(cg + bg, 0.0f), 1.0f);
    out[pix*3 + 2] = fminf(fmaxf(cb + bg, 0.0f), 1.0f);
    out[IMG_W*IMG_H*3 + pix] = dsum;
    out[IMG_W*IMG_H*4 + pix] = acc;
}

// ---------------- launch ----------------
extern "C" void kernel_launch(void* const* d_in, const int* in_sizes, int n_in,
                              void* d_out, int out_size) {
    const float* means3d  = (const float*)d_in[0];
    const float* opacity  = (const float*)d_in[1];
    const float* scale3d  = (const float*)d_in[2];
    const float* features = (const float*)d_in[3];
    const float* viewm    = (const float*)d_in[4];
    const float* projm    = (const float*)d_in[5];
    float* out = (float*)d_out;

    k_project<<<4, 256>>>(means3d, opacity, scale3d, features, viewm, projm);
    k_sort<<<8, 128>>>();
    k_compact<<<NT, 1024>>>();
    k_render<<<256, 256>>>(out);
}

// round 2
// speedup vs baseline: 1.7590x; 1.7590x over previous
#include <cuda_runtime.h>

#define NG      1024
#define IMG_W   256
#define IMG_H   256
#define TILE_SZ 64
#define FOCALF  256.0f         // W / (2 * TAN_FOV)
#define LOG2E   1.4426950408889634f

// Fully fused: project + per-tile compact + per-tile depth sort + composite.
// Grid: 256 blocks (16 tiles x 16 sub-blocks of 16x16 px), 256 threads.
__global__ void __launch_bounds__(256) k_fused(
        const float* __restrict__ means3d,
        const float* __restrict__ opacity,
        const float* __restrict__ scale3d,
        const float* __restrict__ features,
        const float* __restrict__ V,
        const float* __restrict__ P,
        float* __restrict__ out) {

    __shared__ float4 sA[NG];                 // (mx, my, k*log2e, op)   16KB
    __shared__ float4 sB[NG];                 // (r, g, b, depth)        16KB
    __shared__ unsigned long long sKey[NG];   // depth-ordered keys       8KB
    __shared__ unsigned short perm[NG];       // rank -> slot             2KB
    __shared__ int s_cnt;

    const int tid  = threadIdx.x;
    const int tile = blockIdx.x >> 4;
    const int sub  = blockIdx.x & 15;
    const float u0 = (float)((tile & 3) * TILE_SZ);
    const float v0 = (float)((tile >> 2) * TILE_SZ);

    if (tid == 0) s_cnt = 0;
    __syncthreads();

    // ---- project + compact (each thread handles 4 gaussians) ----
    #pragma unroll
    for (int it = 0; it < NG / 256; it++) {
        int g = tid + it * 256;
        float x = means3d[3*g+0], y = means3d[3*g+1], z = means3d[3*g+2];

        float pv0 = x*V[0] + y*V[4] + z*V[8]  + V[12];
        float pv1 = x*V[1] + y*V[5] + z*V[9]  + V[13];
        float pv2 = x*V[2] + y*V[6] + z*V[10] + V[14];
        float pv3 = x*V[3] + y*V[7] + z*V[11] + V[15];

        float ph0 = pv0*P[0] + pv1*P[4] + pv2*P[8]  + pv3*P[12];
        float ph1 = pv0*P[1] + pv1*P[5] + pv2*P[9]  + pv3*P[13];
        float ph3 = pv0*P[3] + pv1*P[7] + pv2*P[11] + pv3*P[15];

        float invw = 1.0f / (ph3 + 1e-6f);
        float mx = ((ph0*invw + 1.0f) * (float)IMG_W - 1.0f) * 0.5f;
        float my = ((ph1*invw + 1.0f) * (float)IMG_H - 1.0f) * 0.5f;

        float tz    = pv2;
        float s2    = scale3d[g] * FOCALF / tz;
        float radii = s2 * 5.0f;
        float k2    = (-0.5f / (s2 * s2)) * LOG2E;  // pre-scaled for ex2

        float rminx = fminf(fmaxf(mx - radii, 0.0f), (float)IMG_W - 1.0f);
        float rminy = fminf(fmaxf(my - radii, 0.0f), (float)IMG_H - 1.0f);
        float rmaxx = fminf(fmaxf(mx + radii, 0.0f), (float)IMG_W - 1.0f);
        float rmaxy = fminf(fmaxf(my + radii, 0.0f), (float)IMG_H - 1.0f);

        bool m = (fminf(rmaxx, u0 + (float)TILE_SZ - 1.0f) > fmaxf(rminx, u0)) &&
                 (fminf(rmaxy, v0 + (float)TILE_SZ - 1.0f) > fmaxf(rminy, v0));
        if (m) {
            int pos = atomicAdd(&s_cnt, 1);
            sA[pos] = make_float4(mx, my, k2, opacity[g]);
            sB[pos] = make_float4(features[3*g+0], features[3*g+1], features[3*g+2], tz);
            unsigned ku = __float_as_uint(tz);
            ku = (ku & 0x80000000u) ? ~ku : (ku | 0x80000000u);
            sKey[pos] = ((unsigned long long)ku << 32) | (unsigned)g;  // unique, stable
        }
    }
    __syncthreads();
    const int cnt = s_cnt;

    // ---- rank sort of the compacted list (cnt is small, ~100) ----
    for (int i = tid; i < cnt; i += 256) {
        unsigned long long k = sKey[i];
        int r = 0;
        for (int j = 0; j < cnt; j++) r += (sKey[j] < k) ? 1 : 0;
        perm[r] = (unsigned short)i;
    }
    __syncthreads();

    // ---- composite 16x16 pixels, front-to-back ----
    int px = (tile & 3) * TILE_SZ + (sub & 3) * 16 + (tid & 15);
    int py = (tile >> 2) * TILE_SZ + (sub >> 2) * 16 + (tid >> 4);
    float fx = (float)px, fy = (float)py;

    float T = 1.0f, cr = 0.0f, cg = 0.0f, cb = 0.0f, dsum = 0.0f;

    for (int j0 = 0; j0 < cnt; j0 += 32) {
        int jend = min(j0 + 32, cnt);
        #pragma unroll 4
        for (int j = j0; j < jend; j++) {
            int idx = perm[j];
            float4 A = sA[idx];
            float dx = fx - A.x;
            float dy = fy - A.y;
            float d2 = fmaf(dx, dx, dy * dy);
            float e;
            asm("ex2.approx.ftz.f32 %0, %1;" : "=f"(e) : "f"(A.z * d2));
            float a  = fminf(e * A.w, 0.99f);
            float w  = a * T;
            float4 B = sB[idx];
            cr   = fmaf(w, B.x, cr);
            cg   = fmaf(w, B.y, cg);
            cb   = fmaf(w, B.z, cb);
            dsum = fmaf(w, B.w, dsum);
            T    = T * (1.0f - a);           // 4-cycle loop-carried chain
        }
        if (__all_sync(0xffffffffu, T <= 1e-6f)) break;
    }

    float acc = 1.0f - T;   // acc == sum(w) up to fp rounding
    float bg  = T;          // 1 - acc
    int pix = py * IMG_W + px;
    out[pix*3 + 0] = fminf(fmaxf(cr + bg, 0.0f), 1.0f);
    out[pix*3 + 1] = fminf(fmaxf(cg + bg, 0.0f), 1.0f);
    out[pix*3 + 2] = fminf(fmaxf(cb + bg, 0.0f), 1.0f);
    out[IMG_W*IMG_H*3 + pix] = dsum;
    out[IMG_W*IMG_H*4 + pix] = acc;
}

extern "C" void kernel_launch(void* const* d_in, const int* in_sizes, int n_in,
                              void* d_out, int out_size) {
    const float* means3d  = (const float*)d_in[0];
    const float* opacity  = (const float*)d_in[1];
    const float* scale3d  = (const float*)d_in[2];
    const float* features = (const float*)d_in[3];
    const float* viewm    = (const float*)d_in[4];
    const float* projm    = (const float*)d_in[5];
    float* out = (float*)d_out;

    k_fused<<<256, 256>>>(means3d, opacity, scale3d, features, viewm, projm, out);
}

// round 3
// speedup vs baseline: 2.7589x; 1.5685x over previous
#include <cuda_runtime.h>

#define NG      1024
#define IMG_W   256
#define IMG_H   256
#define TILE_SZ 64
#define FOCALF  256.0f
#define LOG2E   1.4426950408889634f

#define BLK_W   32
#define BLK_H   16
#define PAD     2.0f
#define NBLK    ((IMG_W / BLK_W) * (IMG_H / BLK_H))   // 8 x 16 = 128

// One fused kernel: project -> (tile AND padded-subrect) cull -> depth-rank
// placement -> front-to-back composite. 128 blocks x 512 threads, 32x16 px each.
__global__ void __launch_bounds__(512) k_fused(
        const float* __restrict__ means3d,
        const float* __restrict__ opacity,
        const float* __restrict__ scale3d,
        const float* __restrict__ features,
        const float* __restrict__ V,
        const float* __restrict__ P,
        float* __restrict__ out) {

    __shared__ float4 sA[NG];                 // (mx, my, k*log2e, op)
    __shared__ float4 sB[NG];                 // (r, g, b, depth)
    __shared__ unsigned long long sKey[NG];
    __shared__ int s_cnt;

    const int tid = threadIdx.x;
    const int bx  = blockIdx.x & 7;           // 8 across
    const int by  = blockIdx.x >> 3;          // 16 down
    const int x0  = bx * BLK_W;
    const int y0  = by * BLK_H;

    // parent 64x64 tile bounds (reference mask granularity)
    const float tu0 = (float)((x0 / TILE_SZ) * TILE_SZ);
    const float tv0 = (float)((y0 / TILE_SZ) * TILE_SZ);
    // padded sub-rect bounds
    const float su0 = (float)x0 - PAD;
    const float su1 = (float)(x0 + BLK_W - 1) + PAD;
    const float sv0 = (float)y0 - PAD;
    const float sv1 = (float)(y0 + BLK_H - 1) + PAD;

    if (tid == 0) s_cnt = 0;
    __syncthreads();

    // registers for up to 2 surviving gaussians owned by this thread
    float4 rA[2], rB[2];
    unsigned long long rK[2];
    int nOwn = 0;

    #pragma unroll
    for (int it = 0; it < NG / 512; it++) {
        int g = tid + it * 512;
        float x = means3d[3*g+0], y = means3d[3*g+1], z = means3d[3*g+2];

        float pv0 = x*V[0] + y*V[4] + z*V[8]  + V[12];
        float pv1 = x*V[1] + y*V[5] + z*V[9]  + V[13];
        float pv2 = x*V[2] + y*V[6] + z*V[10] + V[14];
        float pv3 = x*V[3] + y*V[7] + z*V[11] + V[15];

        float ph0 = pv0*P[0] + pv1*P[4] + pv2*P[8]  + pv3*P[12];
        float ph1 = pv0*P[1] + pv1*P[5] + pv2*P[9]  + pv3*P[13];
        float ph3 = pv0*P[3] + pv1*P[7] + pv2*P[11] + pv3*P[15];

        float invw = __fdividef(1.0f, ph3 + 1e-6f);
        float mx = ((ph0*invw + 1.0f) * (float)IMG_W - 1.0f) * 0.5f;
        float my = ((ph1*invw + 1.0f) * (float)IMG_H - 1.0f) * 0.5f;

        float tz    = pv2;
        float s2    = scale3d[g] * FOCALF * __fdividef(1.0f, tz);
        float radii = s2 * 5.0f;
        float k2    = __fdividef(-0.5f * LOG2E, s2 * s2);

        float rminx = fminf(fmaxf(mx - radii, 0.0f), (float)IMG_W - 1.0f);
        float rminy = fminf(fmaxf(my - radii, 0.0f), (float)IMG_H - 1.0f);
        float rmaxx = fminf(fmaxf(mx + radii, 0.0f), (float)IMG_W - 1.0f);
        float rmaxy = fminf(fmaxf(my + radii, 0.0f), (float)IMG_H - 1.0f);

        // exact reference tile mask
        bool mTile = (fminf(rmaxx, tu0 + (float)TILE_SZ - 1.0f) > fmaxf(rminx, tu0)) &&
                     (fminf(rmaxy, tv0 + (float)TILE_SZ - 1.0f) > fmaxf(rminy, tv0));
        // padded sub-rect cull (dropped gaussians are >= 5sigma+PAD from all px)
        bool mSub  = (fminf(rmaxx, su1) > fmaxf(rminx, su0)) &&
                     (fminf(rmaxy, sv1) > fmaxf(rminy, sv0));

        if (mTile && mSub) {
            rA[nOwn] = make_float4(mx, my, k2, opacity[g]);
            rB[nOwn] = make_float4(features[3*g+0], features[3*g+1], features[3*g+2], tz);
            unsigned ku = __float_as_uint(tz);
            ku = (ku & 0x80000000u) ? ~ku : (ku | 0x80000000u);
            rK[nOwn] = ((unsigned long long)ku << 32) | (unsigned)g;  // unique key
            int pos = atomicAdd(&s_cnt, 1);
            sKey[pos] = rK[nOwn];
            nOwn++;
        }
    }
    __syncthreads();
    const int cnt = s_cnt;

    // place owned gaussians at their depth rank (keys unique -> perfect perm)
    for (int o = 0; o < nOwn; o++) {
        unsigned long long k = rK[o];
        int r = 0;
        for (int j = 0; j < cnt; j++) r += (sKey[j] < k) ? 1 : 0;
        sA[r] = rA[o];
        sB[r] = rB[o];
    }
    __syncthreads();

    // ---- composite: 1 px/thread, front-to-back, broadcast smem reads ----
    int px = x0 + (tid & 31);
    int py = y0 + (tid >> 5);
    float fx = (float)px, fy = (float)py;

    float T = 1.0f, cr = 0.0f, cg = 0.0f, cb = 0.0f, dsum = 0.0f;

    for (int j0 = 0; j0 < cnt; j0 += 16) {
        int jend = min(j0 + 16, cnt);
        #pragma unroll 4
        for (int j = j0; j < jend; j++) {
            float4 A = sA[j];
            float dx = fx - A.x;
            float dy = fy - A.y;
            float d2 = fmaf(dx, dx, dy * dy);
            float e;
            asm("ex2.approx.ftz.f32 %0, %1;" : "=f"(e) : "f"(A.z * d2));
            float a = fminf(e * A.w, 0.99f);
            float w = a * T;
            float4 B = sB[j];
            cr   = fmaf(w, B.x, cr);
            cg   = fmaf(w, B.y, cg);
            cb   = fmaf(w, B.z, cb);
            dsum = fmaf(w, B.w, dsum);
            T    = T * (1.0f - a);
        }
        if (__all_sync(0xffffffffu, T <= 1e-6f)) break;
    }

    float acc = 1.0f - T;
    float bg  = T;
    int pix = py * IMG_W + px;
    out[pix*3 + 0] = fminf(fmaxf(cr + bg, 0.0f), 1.0f);
    out[pix*3 + 1] = fminf(fmaxf(cg + bg, 0.0f), 1.0f);
    out[pix*3 + 2] = fminf(fmaxf(cb + bg, 0.0f), 1.0f);
    out[IMG_W*IMG_H*3 + pix] = dsum;
    out[IMG_W*IMG_H*4 + pix] = acc;
}

extern "C" void kernel_launch(void* const* d_in, const int* in_sizes, int n_in,
                              void* d_out, int out_size) {
    const float* means3d  = (const float*)d_in[0];
    const float* opacity  = (const float*)d_in[1];
    const float* scale3d  = (const float*)d_in[2];
    const float* features = (const float*)d_in[3];
    const float* viewm    = (const float*)d_in[4];
    const float* projm    = (const float*)d_in[5];
    float* out = (float*)d_out;

    k_fused<<<NBLK, 512>>>(means3d, opacity, scale3d, features, viewm, projm, out);
}